// round 14
// baseline (speedup 1.0000x reference)
#include <cuda_runtime.h>
#include <cuda_fp16.h>
#include <cstdint>
#include <math.h>

#define B_ 2
#define S_ 2048
#define DM_ 1024
#define H_ 16
#define HD_ 64
#define MTOT (B_ * S_)      // 4096
// 0.125 * log2(e): folded into Q projection so softmax runs in exp2 domain
#define QSCALE 0.18033688f

#define fu __float_as_uint
#define uf __uint_as_float

// Scratch (allocation-free: __device__ globals; referenced ONLY in device code)
__device__ __half g_Q[(size_t)B_ * H_ * S_ * HD_];   // [B,H,S,HD], fp16, pre-scaled
__device__ __half g_K[(size_t)B_ * H_ * S_ * HD_];   // [B,H,S,HD], fp16
__device__ __half g_Vt[(size_t)B_ * H_ * HD_ * S_];  // [B,H,HD,S] TRANSPOSED, fp16
__device__ __half g_O[(size_t)B_ * S_ * DM_];        // [B*S,DM], fp16
__device__ __half g_Xq[(size_t)MTOT * DM_];          // fp16 inputs
__device__ __half g_Xk[(size_t)MTOT * DM_];
__device__ __half g_Xv[(size_t)MTOT * DM_];
__device__ __half g_Wq[(size_t)DM_ * DM_];           // fp16 weights
__device__ __half g_Wk[(size_t)DM_ * DM_];
__device__ __half g_Wv[(size_t)DM_ * DM_];
__device__ __half g_Wo[(size_t)DM_ * DM_];

// Grid barrier counters (two-counter scheme; last exiter resets both -> replay-safe)
__device__ int g_barA[3];
__device__ int g_barE[3];

__device__ __forceinline__ void gridbar(int i) {
    __syncthreads();
    if (threadIdx.x == 0) {
        __threadfence();
        atomicAdd(&g_barA[i], 1);
        while (*((volatile int*)&g_barA[i]) < (int)gridDim.x) { }
        const int e = atomicAdd(&g_barE[i], 1);
        if (e == (int)gridDim.x - 1) {
            *((volatile int*)&g_barA[i]) = 0;
            *((volatile int*)&g_barE[i]) = 0;
            __threadfence();
        }
    }
    __syncthreads();
}

__device__ __forceinline__ uint32_t pk2(float a, float b) {
    __half2 h = __floats2half2_rn(a, b);
    return *reinterpret_cast<uint32_t*>(&h);
}

__device__ __forceinline__ float ex2(float x) {
    float r;
    asm("ex2.approx.ftz.f32 %0, %1;" : "=f"(r) : "f"(x));
    return r;
}

__device__ __forceinline__ void mma_f16(float c[4],
                                        uint32_t a0, uint32_t a1, uint32_t a2, uint32_t a3,
                                        uint32_t b0, uint32_t b1) {
    asm volatile(
        "mma.sync.aligned.m16n8k16.row.col.f32.f16.f16.f32 "
        "{%0,%1,%2,%3}, {%4,%5,%6,%7}, {%8,%9}, {%0,%1,%2,%3};\n"
        : "+f"(c[0]), "+f"(c[1]), "+f"(c[2]), "+f"(c[3])
        : "r"(a0), "r"(a1), "r"(a2), "r"(a3), "r"(b0), "r"(b1));
}

__device__ __forceinline__ void ldsm4(uint32_t r[4], uint32_t addr) {
    asm volatile("ldmatrix.sync.aligned.m8n8.x4.shared.b16 {%0,%1,%2,%3}, [%4];"
                 : "=r"(r[0]), "=r"(r[1]), "=r"(r[2]), "=r"(r[3]) : "r"(addr));
}

__device__ __forceinline__ void cpa16(uint32_t dst, const void* src) {
    asm volatile("cp.async.cg.shared.global [%0], [%1], 16;" :: "r"(dst), "l"(src));
}
#define CP_COMMIT() asm volatile("cp.async.commit_group;")
#define CP_WAIT0()  asm volatile("cp.async.wait_group 0;")

#define LDH 72
#define GTILEB (128 * LDH * 2)   // 18432
#define VT_LD 136
#define KB (128 * LDH * 2)       // 18432 per K buffer
#define VB (64 * VT_LD * 2)      // 17408 per V buffer

// ---------------------------------------------------------------------------
// Phase 0: convert inputs and weights to fp16 (grid-strided over 7 tensors).
// ---------------------------------------------------------------------------
__device__ __forceinline__ void prep_phase(
    const float* __restrict__ q, const float* __restrict__ k,
    const float* __restrict__ v, const float* __restrict__ wq,
    const float* __restrict__ wk, const float* __restrict__ wv,
    const float* __restrict__ wo)
{
    const float* srcs[7] = {q, k, v, wq, wk, wv, wo};
    __half* dsts[7] = {g_Xq, g_Xk, g_Xv, g_Wq, g_Wk, g_Wv, g_Wo};
    const int ns[7] = {MTOT * DM_, MTOT * DM_, MTOT * DM_,
                       DM_ * DM_, DM_ * DM_, DM_ * DM_, DM_ * DM_};
    const int stride = gridDim.x * blockDim.x;
#pragma unroll 1
    for (int segi = 0; segi < 7; segi++) {
        const float* src = srcs[segi];
        __half* dst = dsts[segi];
        const int n8 = ns[segi] >> 3;
        for (int i = blockIdx.x * blockDim.x + threadIdx.x; i < n8; i += stride) {
            float4 x0 = ((const float4*)src)[2 * i];
            float4 x1 = ((const float4*)src)[2 * i + 1];
            uint4 o;
            o.x = pk2(x0.x, x0.y); o.y = pk2(x0.z, x0.w);
            o.z = pk2(x1.x, x1.y); o.w = pk2(x1.z, x1.w);
            ((uint4*)dst)[i] = o;
        }
    }
}

// ---------------------------------------------------------------------------
// GEMM phase (identical internals to round 12/13).
// MODE 0: X=g_O, W=g_Wo -> fp32 out (256 items).
// MODE 1: merged QKV, 768 items (z==0 Q scaled; z==2 V transposed).
// ---------------------------------------------------------------------------
template <int MODE>
__device__ __forceinline__ void gemm_phase(
    __half* smh, const float* __restrict__ bias0, const float* __restrict__ bias1,
    const float* __restrict__ bias2, float* __restrict__ Y)
{
    const uint32_t sA = (uint32_t)__cvta_generic_to_shared(smh);
    const uint32_t sB = sA + GTILEB;

    const int tid  = threadIdx.x;
    const int warp = tid >> 5, lane = tid & 31;
    const int g  = lane >> 2, tg = lane & 3;
    const int wm = warp >> 2, wn = warp & 3;

    const int a_base = (wm * 64 + (lane & 15)) * LDH + ((lane >> 4) << 3);
    const int b_base = (wn * 32 + ((lane >> 4) << 3) + (lane & 7)) * LDH
                     + (((lane >> 3) & 1) << 3);

    const int NITEMS = (MODE == 0) ? 256 : 768;

    for (int item = blockIdx.x; item < NITEMS; item += gridDim.x) {
        const int z = (MODE == 0) ? 0 : (item >> 8);
        const int rem = item & 255;
        const int bn = (rem & 7) * 128;
        const int bm = (rem >> 3) * 128;

        const __half* X = (MODE == 0) ? g_O : (z == 0) ? g_Xq : (z == 1) ? g_Xk : g_Xv;
        const __half* W = (MODE == 0) ? g_Wo : (z == 0) ? g_Wq : (z == 1) ? g_Wk : g_Wv;
        const float* bias = (MODE == 0) ? bias0 : (z == 0) ? bias0 : (z == 1) ? bias1 : bias2;

        float acc[4][4][4];
#pragma unroll
        for (int i = 0; i < 4; i++)
#pragma unroll
            for (int j = 0; j < 4; j++)
#pragma unroll
                for (int k = 0; k < 4; k++) acc[i][j][k] = 0.0f;

#pragma unroll
        for (int i = 0; i < 4; i++) {
            const int f = tid + 256 * i;
            const int row = f >> 3, ch = (f & 7) << 3;
            const uint32_t off = (uint32_t)(row * LDH + ch) << 1;
            cpa16(sA + off, X + (size_t)(bm + row) * DM_ + ch);
            cpa16(sB + off, W + (size_t)(bn + row) * DM_ + ch);
        }
        CP_COMMIT();

        for (int t = 0; t < 16; t++) {
            CP_WAIT0();
            __syncthreads();

            if (t + 1 < 16) {
                const int k0 = (t + 1) * 64;
                const uint32_t bufo = (uint32_t)(((t + 1) & 1) * 2 * GTILEB);
#pragma unroll
                for (int i = 0; i < 4; i++) {
                    const int f = tid + 256 * i;
                    const int row = f >> 3, ch = (f & 7) << 3;
                    const uint32_t off = bufo + ((uint32_t)(row * LDH + ch) << 1);
                    cpa16(sA + off, X + (size_t)(bm + row) * DM_ + k0 + ch);
                    cpa16(sB + off, W + (size_t)(bn + row) * DM_ + k0 + ch);
                }
                CP_COMMIT();
            }

            const uint32_t bufb = (uint32_t)((t & 1) * 2 * GTILEB);
            const uint32_t sAb = sA + bufb;
            const uint32_t sBb = sB + bufb;

            uint32_t af[2][4][4], bf[2][2][4];
#pragma unroll
            for (int mi = 0; mi < 4; mi++)
                ldsm4(af[0][mi], sAb + ((uint32_t)(a_base + mi * 16 * LDH) << 1));
#pragma unroll
            for (int p = 0; p < 2; p++)
                ldsm4(bf[0][p], sBb + ((uint32_t)(b_base + p * 16 * LDH) << 1));

#pragma unroll
            for (int ks = 0; ks < 4; ks++) {
                const int cur = ks & 1, nxt = cur ^ 1;
                if (ks < 3) {
                    const int kk = (ks + 1) * 16;
#pragma unroll
                    for (int mi = 0; mi < 4; mi++)
                        ldsm4(af[nxt][mi],
                              sAb + ((uint32_t)(a_base + mi * 16 * LDH + kk) << 1));
#pragma unroll
                    for (int p = 0; p < 2; p++)
                        ldsm4(bf[nxt][p],
                              sBb + ((uint32_t)(b_base + p * 16 * LDH + kk) << 1));
                }
#pragma unroll
                for (int mi = 0; mi < 4; mi++)
#pragma unroll
                    for (int p = 0; p < 2; p++) {
                        mma_f16(acc[mi][2 * p],
                                af[cur][mi][0], af[cur][mi][1], af[cur][mi][2], af[cur][mi][3],
                                bf[cur][p][0], bf[cur][p][1]);
                        mma_f16(acc[mi][2 * p + 1],
                                af[cur][mi][0], af[cur][mi][1], af[cur][mi][2], af[cur][mi][3],
                                bf[cur][p][2], bf[cur][p][3]);
                    }
            }
        }
        __syncthreads();

#pragma unroll
        for (int mi = 0; mi < 4; mi++) {
#pragma unroll
            for (int ni = 0; ni < 4; ni++) {
                const int m = bm + wm * 64 + mi * 16 + g;
                const int n = bn + wn * 32 + ni * 8 + 2 * tg;
                const float b0 = bias[n], b1 = bias[n + 1];
                float v00 = acc[mi][ni][0] + b0;
                float v01 = acc[mi][ni][1] + b1;
                float v10 = acc[mi][ni][2] + b0;
                float v11 = acc[mi][ni][3] + b1;
                if (MODE == 0) {
                    *(float2*)(Y + (size_t)m * DM_ + n)       = make_float2(v00, v01);
                    *(float2*)(Y + (size_t)(m + 8) * DM_ + n) = make_float2(v10, v11);
                } else {
                    if (z == 0) { v00 *= QSCALE; v01 *= QSCALE; v10 *= QSCALE; v11 *= QSCALE; }
                    const int h_ = n >> 6, d_ = n & (HD_ - 1);
                    if (z == 2) {
                        {
                            const int b_ = m >> 11, s_ = m & (S_ - 1);
                            __half* base = g_Vt + (((size_t)b_ * H_ + h_) * HD_ + d_) * S_ + s_;
                            base[0]  = __float2half_rn(v00);
                            base[S_] = __float2half_rn(v01);
                        }
                        {
                            const int m2 = m + 8;
                            const int b_ = m2 >> 11, s_ = m2 & (S_ - 1);
                            __half* base = g_Vt + (((size_t)b_ * H_ + h_) * HD_ + d_) * S_ + s_;
                            base[0]  = __float2half_rn(v10);
                            base[S_] = __float2half_rn(v11);
                        }
                    } else {
                        __half* dst = (z == 0) ? g_Q : g_K;
                        {
                            const int b_ = m >> 11, s_ = m & (S_ - 1);
                            *(uint32_t*)(dst + (((size_t)b_ * H_ + h_) * S_ + s_) * HD_ + d_) =
                                pk2(v00, v01);
                        }
                        {
                            const int m2 = m + 8;
                            const int b_ = m2 >> 11, s_ = m2 & (S_ - 1);
                            *(uint32_t*)(dst + (((size_t)b_ * H_ + h_) * S_ + s_) * HD_ + d_) =
                                pk2(v10, v11);
                        }
                    }
                }
            }
        }
    }
}

// ---------------------------------------------------------------------------
// Attention phase (identical internals to round 13: Bc=128, 64-col chunks,
// exp2-domain softmax-one, O^T = V^T @ P^T).
// ---------------------------------------------------------------------------
__device__ __forceinline__ void attn_phase(__half* smh)
{
    __half* Qs = smh;                           // 128*72 halves (reused as Ps)
    const uint32_t sQ = (uint32_t)__cvta_generic_to_shared(Qs);
    const uint32_t sK = sQ + 128 * LDH * 2;     // [2][128][72]
    const uint32_t sV = sK + 2 * KB;            // [2][64][136]

    const int tid  = threadIdx.x;
    const int warp = tid >> 5, lane = tid & 31;
    const int g = lane >> 2, tg = lane & 3;

    const int q_base  = (warp * 16 + (lane & 15)) * LDH + ((lane >> 4) << 3);
    const int k_base  = (((lane >> 4) << 3) + (lane & 7)) * LDH
                      + (((lane >> 3) & 1) << 3);
    const int p_base  = q_base;
    const int vt_base = (lane & 15) * VT_LD + ((lane >> 4) << 3);
    const int qrow = warp * 16 + g;

    for (int item = blockIdx.x; item < 512; item += gridDim.x) {
        const int bh = item & 31;
        const int q0blk = (item >> 5) * 128;
        const int b = bh >> 4, h = bh & (H_ - 1);

        const __half* Qg  = g_Q + ((size_t)bh * S_ + q0blk) * HD_;
        const __half* Kg  = g_K + (size_t)bh * S_ * HD_;
        const __half* Vtg = g_Vt + (size_t)bh * HD_ * S_;

#pragma unroll
        for (int i = 0; i < 4; i++) {
            const int f = tid + 256 * i;
            const int krow = f >> 3, kch = (f & 7) << 3;
            cpa16(sK + ((uint32_t)(krow * LDH + kch) << 1), Kg + (size_t)krow * HD_ + kch);
            const int vrow = f >> 4, vch = (f & 15) << 3;
            cpa16(sV + ((uint32_t)(vrow * VT_LD + vch) << 1), Vtg + (size_t)vrow * S_ + vch);
        }
        CP_COMMIT();

#pragma unroll
        for (int i = 0; i < 4; i++) {
            const int f = tid + 256 * i;
            const int row = f >> 3, ch = (f & 7) << 3;
            *(uint4*)((char*)Qs + ((size_t)(row * LDH + ch) << 1)) =
                *(const uint4*)(Qg + (size_t)row * HD_ + ch);
        }
        __syncthreads();

        uint32_t qf[4][4];
#pragma unroll
        for (int ks = 0; ks < 4; ks++)
            ldsm4(qf[ks], sQ + ((uint32_t)(q_base + ks * 16) << 1));
        __syncthreads();   // Qs now reusable as Ps

        float oacc[4][2][4];
#pragma unroll
        for (int i = 0; i < 4; i++)
#pragma unroll
            for (int j = 0; j < 2; j++)
#pragma unroll
                for (int k = 0; k < 4; k++) oacc[i][j][k] = 0.0f;

        float m0 = 0.0f, m1 = 0.0f;   // virtual zero logit (log2 domain)
        float l0 = 1.0f, l1 = 1.0f;

        for (int t = 0; t < 16; t++) {
            CP_WAIT0();
            __syncthreads();

            if (t + 1 < 16) {
                const size_t gofs = (size_t)(t + 1) * 128;
                const uint32_t bK = (uint32_t)(((t + 1) & 1) * KB);
                const uint32_t bV = (uint32_t)(((t + 1) & 1) * VB);
#pragma unroll
                for (int i = 0; i < 4; i++) {
                    const int f = tid + 256 * i;
                    const int krow = f >> 3, kch = (f & 7) << 3;
                    cpa16(sK + bK + ((uint32_t)(krow * LDH + kch) << 1),
                          Kg + (gofs + krow) * HD_ + kch);
                    const int vrow = f >> 4, vch = (f & 15) << 3;
                    cpa16(sV + bV + ((uint32_t)(vrow * VT_LD + vch) << 1),
                          Vtg + (size_t)vrow * S_ + gofs + vch);
                }
                CP_COMMIT();
            }

            const uint32_t sKb = sK + (uint32_t)((t & 1) * KB);
            const uint32_t sVb = sV + (uint32_t)((t & 1) * VB);

#pragma unroll
            for (int c = 0; c < 2; c++) {
                const int colbase = c * 64;
                float s[8][4];
#pragma unroll
                for (int nt = 0; nt < 8; nt++)
                    s[nt][0] = s[nt][1] = s[nt][2] = s[nt][3] = 0.0f;

#pragma unroll
                for (int ks = 0; ks < 4; ks++) {
#pragma unroll
                    for (int p = 0; p < 4; p++) {
                        uint32_t kf[4];
                        ldsm4(kf, sKb + ((uint32_t)(k_base + (colbase + p * 16) * LDH
                                                    + ks * 16) << 1));
                        mma_f16(s[2 * p],     qf[ks][0], qf[ks][1], qf[ks][2], qf[ks][3],
                                kf[0], kf[1]);
                        mma_f16(s[2 * p + 1], qf[ks][0], qf[ks][1], qf[ks][2], qf[ks][3],
                                kf[2], kf[3]);
                    }
                }

                float rm0 = m0, rm1 = m1;
#pragma unroll
                for (int nt = 0; nt < 8; nt++) {
                    rm0 = fmaxf(rm0, fmaxf(s[nt][0], s[nt][1]));
                    rm1 = fmaxf(rm1, fmaxf(s[nt][2], s[nt][3]));
                }
                rm0 = fmaxf(rm0, __shfl_xor_sync(0xffffffffu, rm0, 1));
                rm0 = fmaxf(rm0, __shfl_xor_sync(0xffffffffu, rm0, 2));
                rm1 = fmaxf(rm1, __shfl_xor_sync(0xffffffffu, rm1, 1));
                rm1 = fmaxf(rm1, __shfl_xor_sync(0xffffffffu, rm1, 2));

                const float corr0 = ex2(m0 - rm0);
                const float corr1 = ex2(m1 - rm1);

                float ls0 = 0.0f, ls1 = 0.0f;
#pragma unroll
                for (int nt = 0; nt < 8; nt++) {
                    const float p00 = ex2(s[nt][0] - rm0);
                    const float p01 = ex2(s[nt][1] - rm0);
                    const float p10 = ex2(s[nt][2] - rm1);
                    const float p11 = ex2(s[nt][3] - rm1);
                    ls0 += p00 + p01;
                    ls1 += p10 + p11;
                    const int col = nt * 8 + 2 * tg;          // mod-64 column inside Ps
                    *(uint32_t*)&Qs[qrow * LDH + col]       = pk2(p00, p01);
                    *(uint32_t*)&Qs[(qrow + 8) * LDH + col] = pk2(p10, p11);
                }
                ls0 += __shfl_xor_sync(0xffffffffu, ls0, 1);
                ls0 += __shfl_xor_sync(0xffffffffu, ls0, 2);
                ls1 += __shfl_xor_sync(0xffffffffu, ls1, 1);
                ls1 += __shfl_xor_sync(0xffffffffu, ls1, 2);
                l0 = l0 * corr0 + ls0; m0 = rm0;
                l1 = l1 * corr1 + ls1; m1 = rm1;
                __syncwarp();

#pragma unroll
                for (int nt = 0; nt < 2; nt++) {
                    const int ql0 = 2 * tg, ql1 = 2 * tg + 1;
                    float c0a = __shfl_sync(0xffffffffu, corr0, ql0 * 4);
                    float c0b = __shfl_sync(0xffffffffu, corr1, ql0 * 4);
                    float c1a = __shfl_sync(0xffffffffu, corr0, ql1 * 4);
                    float c1b = __shfl_sync(0xffffffffu, corr1, ql1 * 4);
                    const float cq0 = (nt == 0) ? c0a : c0b;
                    const float cq1 = (nt == 0) ? c1a : c1b;
#pragma unroll
                    for (int dt = 0; dt < 4; dt++) {
                        oacc[dt][nt][0] *= cq0;
                        oacc[dt][nt][1] *= cq1;
                        oacc[dt][nt][2] *= cq0;
                        oacc[dt][nt][3] *= cq1;
                    }
                }

#pragma unroll
                for (int ks2 = 0; ks2 < 4; ks2++) {
                    uint32_t pr[4];
                    ldsm4(pr, sQ + ((uint32_t)(p_base + ks2 * 16) << 1));
#pragma unroll
                    for (int dt = 0; dt < 4; dt++) {
                        uint32_t vf[4];
                        ldsm4(vf, sVb + ((uint32_t)(vt_base + dt * 16 * VT_LD
                                                    + colbase + ks2 * 16) << 1));
                        mma_f16(oacc[dt][0], vf[0], vf[1], vf[2], vf[3], pr[0], pr[2]);
                        mma_f16(oacc[dt][1], vf[0], vf[1], vf[2], vf[3], pr[1], pr[3]);
                    }
                }
                __syncwarp();   // P consumed before next chunk overwrites it
            }
        }

        const float inv0 = 1.0f / l0;
        const float inv1 = 1.0f / l1;
        float ivq[2][2];
#pragma unroll
        for (int nt = 0; nt < 2; nt++) {
            const int ql0 = 2 * tg, ql1 = 2 * tg + 1;
            float a0 = __shfl_sync(0xffffffffu, inv0, ql0 * 4);
            float b0 = __shfl_sync(0xffffffffu, inv1, ql0 * 4);
            float a1 = __shfl_sync(0xffffffffu, inv0, ql1 * 4);
            float b1 = __shfl_sync(0xffffffffu, inv1, ql1 * 4);
            ivq[nt][0] = (nt == 0) ? a0 : b0;
            ivq[nt][1] = (nt == 0) ? a1 : b1;
        }

        const size_t obase = ((size_t)(b * S_ + q0blk + warp * 16)) * DM_ + h * HD_;
#pragma unroll
        for (int dt = 0; dt < 4; dt++) {
#pragma unroll
            for (int nt = 0; nt < 2; nt++) {
                const int d  = dt * 16 + g;
                const int ql = nt * 8 + 2 * tg;
                g_O[obase + (size_t)ql * DM_ + d]           = __float2half_rn(oacc[dt][nt][0] * ivq[nt][0]);
                g_O[obase + (size_t)(ql + 1) * DM_ + d]     = __float2half_rn(oacc[dt][nt][1] * ivq[nt][1]);
                g_O[obase + (size_t)ql * DM_ + d + 8]       = __float2half_rn(oacc[dt][nt][2] * ivq[nt][0]);
                g_O[obase + (size_t)(ql + 1) * DM_ + d + 8] = __float2half_rn(oacc[dt][nt][3] * ivq[nt][1]);
            }
        }
        __syncthreads();   // smem safe to reuse for next item
    }
}

// ---------------------------------------------------------------------------
// Fused persistent kernel: prep | barrier | QKV | barrier | attn | barrier | out
// Grid must be exactly co-resident: 296 CTAs = 2/SM x 148 SMs.
// ---------------------------------------------------------------------------
__global__ __launch_bounds__(256, 2)
void fused_mha(const float* __restrict__ q, const float* __restrict__ k,
               const float* __restrict__ v,
               const float* __restrict__ wq, const float* __restrict__ bq,
               const float* __restrict__ wk, const float* __restrict__ bk,
               const float* __restrict__ wv, const float* __restrict__ bv,
               const float* __restrict__ wo, const float* __restrict__ bo,
               float* __restrict__ out)
{
    extern __shared__ __half smh[];

    prep_phase(q, k, v, wq, wk, wv, wo);
    gridbar(0);

    gemm_phase<1>(smh, bq, bk, bv, nullptr);
    gridbar(1);

    attn_phase(smh);
    gridbar(2);

    gemm_phase<0>(smh, bo, nullptr, nullptr, out);
}

// ---------------------------------------------------------------------------
// Launch (only harness pointers cross the host/device boundary)
// ---------------------------------------------------------------------------
extern "C" void kernel_launch(void* const* d_in, const int* in_sizes, int n_in,
                              void* d_out, int out_size)
{
    const int fused_smem = 128 * LDH * 2 + 2 * KB + 2 * VB;   // 90112 (union; gemm needs 73728)

    cudaFuncSetAttribute(fused_mha, cudaFuncAttributeMaxDynamicSharedMemorySize, fused_smem);

    fused_mha<<<296, 256, fused_smem>>>(
        (const float*)d_in[0], (const float*)d_in[1], (const float*)d_in[2],
        (const float*)d_in[3], (const float*)d_in[4],
        (const float*)d_in[5], (const float*)d_in[6],
        (const float*)d_in[7], (const float*)d_in[8],
        (const float*)d_in[9], (const float*)d_in[10],
        (float*)d_out);
}

// round 15
// speedup vs baseline: 1.0710x; 1.0710x over previous
#include <cuda_runtime.h>
#include <cuda_fp16.h>
#include <cstdint>
#include <math.h>

#define B_ 2
#define S_ 2048
#define DM_ 1024
#define H_ 16
#define HD_ 64
#define MTOT (B_ * S_)      // 4096
// 0.125 * log2(e): folded into Q projection so softmax runs in exp2 domain
#define QSCALE 0.18033688f

#define fu __float_as_uint
#define uf __uint_as_float

// Scratch (allocation-free: __device__ globals; referenced ONLY in device code)
__device__ __half g_Q[(size_t)B_ * H_ * S_ * HD_];   // [B,H,S,HD], fp16, pre-scaled
__device__ __half g_K[(size_t)B_ * H_ * S_ * HD_];   // [B,H,S,HD], fp16
__device__ __half g_Vt[(size_t)B_ * H_ * HD_ * S_];  // [B,H,HD,S] TRANSPOSED, fp16
__device__ __half g_O[(size_t)B_ * S_ * DM_];        // [B*S,DM], fp16
__device__ __half g_Xq[(size_t)MTOT * DM_];          // fp16 inputs
__device__ __half g_Xk[(size_t)MTOT * DM_];
__device__ __half g_Xv[(size_t)MTOT * DM_];
__device__ __half g_Wq[(size_t)DM_ * DM_];           // fp16 weights
__device__ __half g_Wk[(size_t)DM_ * DM_];
__device__ __half g_Wv[(size_t)DM_ * DM_];
__device__ __half g_Wo[(size_t)DM_ * DM_];

__device__ __forceinline__ uint32_t pk2(float a, float b) {
    __half2 h = __floats2half2_rn(a, b);
    return *reinterpret_cast<uint32_t*>(&h);
}

__device__ __forceinline__ float ex2(float x) {
    float r;
    asm("ex2.approx.ftz.f32 %0, %1;" : "=f"(r) : "f"(x));
    return r;
}

__device__ __forceinline__ void mma_f16(float c[4],
                                        uint32_t a0, uint32_t a1, uint32_t a2, uint32_t a3,
                                        uint32_t b0, uint32_t b1) {
    asm volatile(
        "mma.sync.aligned.m16n8k16.row.col.f32.f16.f16.f32 "
        "{%0,%1,%2,%3}, {%4,%5,%6,%7}, {%8,%9}, {%0,%1,%2,%3};\n"
        : "+f"(c[0]), "+f"(c[1]), "+f"(c[2]), "+f"(c[3])
        : "r"(a0), "r"(a1), "r"(a2), "r"(a3), "r"(b0), "r"(b1));
}

// fp16-ACCUMULATE variant (tests whether legacy HMMA f16-acc is double rate)
__device__ __forceinline__ void mma_f16h(uint32_t c[2],
                                         uint32_t a0, uint32_t a1, uint32_t a2, uint32_t a3,
                                         uint32_t b0, uint32_t b1) {
    asm volatile(
        "mma.sync.aligned.m16n8k16.row.col.f16.f16.f16.f16 "
        "{%0,%1}, {%2,%3,%4,%5}, {%6,%7}, {%0,%1};\n"
        : "+r"(c[0]), "+r"(c[1])
        : "r"(a0), "r"(a1), "r"(a2), "r"(a3), "r"(b0), "r"(b1));
}

__device__ __forceinline__ void ldsm4(uint32_t r[4], uint32_t addr) {
    asm volatile("ldmatrix.sync.aligned.m8n8.x4.shared.b16 {%0,%1,%2,%3}, [%4];"
                 : "=r"(r[0]), "=r"(r[1]), "=r"(r[2]), "=r"(r[3]) : "r"(addr));
}

__device__ __forceinline__ void cpa16(uint32_t dst, const void* src) {
    asm volatile("cp.async.cg.shared.global [%0], [%1], 16;" :: "r"(dst), "l"(src));
}
#define CP_COMMIT() asm volatile("cp.async.commit_group;")
#define CP_WAIT0()  asm volatile("cp.async.wait_group 0;")

// ---------------------------------------------------------------------------
// Prep: convert inputs and weights to fp16 (rn) once (elementwise).
// ---------------------------------------------------------------------------
__global__ void prep_half(const float* __restrict__ q, const float* __restrict__ k,
                          const float* __restrict__ v, const float* __restrict__ wq,
                          const float* __restrict__ wk, const float* __restrict__ wv,
                          const float* __restrict__ wo)
{
    const float* src; __half* dst; int n;
    switch (blockIdx.y) {
        case 0: src = q;  dst = g_Xq; n = MTOT * DM_; break;
        case 1: src = k;  dst = g_Xk; n = MTOT * DM_; break;
        case 2: src = v;  dst = g_Xv; n = MTOT * DM_; break;
        case 3: src = wq; dst = g_Wq; n = DM_ * DM_;  break;
        case 4: src = wk; dst = g_Wk; n = DM_ * DM_;  break;
        case 5: src = wv; dst = g_Wv; n = DM_ * DM_;  break;
        default: src = wo; dst = g_Wo; n = DM_ * DM_; break;
    }
    const int n8 = n >> 3;
    for (int i = blockIdx.x * blockDim.x + threadIdx.x; i < n8;
         i += gridDim.x * blockDim.x) {
        float4 x0 = ((const float4*)src)[2 * i];
        float4 x1 = ((const float4*)src)[2 * i + 1];
        uint4 o;
        o.x = pk2(x0.x, x0.y); o.y = pk2(x0.z, x0.w);
        o.z = pk2(x1.x, x1.y); o.w = pk2(x1.z, x1.w);
        ((uint4*)dst)[i] = o;
    }
}

// ---------------------------------------------------------------------------
// fp16 GEMM (persistent, identical to round 12 — fp32 accumulate).
// ---------------------------------------------------------------------------
#define LDH 72
#define GTILEB (128 * LDH * 2)   // 18432

template <int MODE>
__global__ __launch_bounds__(256, 2)
void gemm_f16(const float* __restrict__ bias0, const float* __restrict__ bias1,
              const float* __restrict__ bias2, float* __restrict__ Y)
{
    extern __shared__ __half smh[];
    const uint32_t sA = (uint32_t)__cvta_generic_to_shared(smh);
    const uint32_t sB = sA + GTILEB;

    const int tid  = threadIdx.x;
    const int warp = tid >> 5, lane = tid & 31;
    const int g  = lane >> 2, tg = lane & 3;
    const int wm = warp >> 2, wn = warp & 3;

    const int a_base = (wm * 64 + (lane & 15)) * LDH + ((lane >> 4) << 3);
    const int b_base = (wn * 32 + ((lane >> 4) << 3) + (lane & 7)) * LDH
                     + (((lane >> 3) & 1) << 3);

    const int NITEMS = (MODE == 0) ? 256 : 768;

    for (int item = blockIdx.x; item < NITEMS; item += gridDim.x) {
        const int z = (MODE == 0) ? 0 : (item >> 8);
        const int rem = item & 255;
        const int bn = (rem & 7) * 128;
        const int bm = (rem >> 3) * 128;

        const __half* X = (MODE == 0) ? g_O : (z == 0) ? g_Xq : (z == 1) ? g_Xk : g_Xv;
        const __half* W = (MODE == 0) ? g_Wo : (z == 0) ? g_Wq : (z == 1) ? g_Wk : g_Wv;
        const float* bias = (MODE == 0) ? bias0 : (z == 0) ? bias0 : (z == 1) ? bias1 : bias2;

        float acc[4][4][4];
#pragma unroll
        for (int i = 0; i < 4; i++)
#pragma unroll
            for (int j = 0; j < 4; j++)
#pragma unroll
                for (int k = 0; k < 4; k++) acc[i][j][k] = 0.0f;

#pragma unroll
        for (int i = 0; i < 4; i++) {
            const int f = tid + 256 * i;
            const int row = f >> 3, ch = (f & 7) << 3;
            const uint32_t off = (uint32_t)(row * LDH + ch) << 1;
            cpa16(sA + off, X + (size_t)(bm + row) * DM_ + ch);
            cpa16(sB + off, W + (size_t)(bn + row) * DM_ + ch);
        }
        CP_COMMIT();

        for (int t = 0; t < 16; t++) {
            CP_WAIT0();
            __syncthreads();

            if (t + 1 < 16) {
                const int k0 = (t + 1) * 64;
                const uint32_t bufo = (uint32_t)(((t + 1) & 1) * 2 * GTILEB);
#pragma unroll
                for (int i = 0; i < 4; i++) {
                    const int f = tid + 256 * i;
                    const int row = f >> 3, ch = (f & 7) << 3;
                    const uint32_t off = bufo + ((uint32_t)(row * LDH + ch) << 1);
                    cpa16(sA + off, X + (size_t)(bm + row) * DM_ + k0 + ch);
                    cpa16(sB + off, W + (size_t)(bn + row) * DM_ + k0 + ch);
                }
                CP_COMMIT();
            }

            const uint32_t bufb = (uint32_t)((t & 1) * 2 * GTILEB);
            const uint32_t sAb = sA + bufb;
            const uint32_t sBb = sB + bufb;

            uint32_t af[2][4][4], bf[2][2][4];
#pragma unroll
            for (int mi = 0; mi < 4; mi++)
                ldsm4(af[0][mi], sAb + ((uint32_t)(a_base + mi * 16 * LDH) << 1));
#pragma unroll
            for (int p = 0; p < 2; p++)
                ldsm4(bf[0][p], sBb + ((uint32_t)(b_base + p * 16 * LDH) << 1));

#pragma unroll
            for (int ks = 0; ks < 4; ks++) {
                const int cur = ks & 1, nxt = cur ^ 1;
                if (ks < 3) {
                    const int kk = (ks + 1) * 16;
#pragma unroll
                    for (int mi = 0; mi < 4; mi++)
                        ldsm4(af[nxt][mi],
                              sAb + ((uint32_t)(a_base + mi * 16 * LDH + kk) << 1));
#pragma unroll
                    for (int p = 0; p < 2; p++)
                        ldsm4(bf[nxt][p],
                              sBb + ((uint32_t)(b_base + p * 16 * LDH + kk) << 1));
                }
#pragma unroll
                for (int mi = 0; mi < 4; mi++)
#pragma unroll
                    for (int p = 0; p < 2; p++) {
                        mma_f16(acc[mi][2 * p],
                                af[cur][mi][0], af[cur][mi][1], af[cur][mi][2], af[cur][mi][3],
                                bf[cur][p][0], bf[cur][p][1]);
                        mma_f16(acc[mi][2 * p + 1],
                                af[cur][mi][0], af[cur][mi][1], af[cur][mi][2], af[cur][mi][3],
                                bf[cur][p][2], bf[cur][p][3]);
                    }
            }
        }
        __syncthreads();

#pragma unroll
        for (int mi = 0; mi < 4; mi++) {
#pragma unroll
            for (int ni = 0; ni < 4; ni++) {
                const int m = bm + wm * 64 + mi * 16 + g;
                const int n = bn + wn * 32 + ni * 8 + 2 * tg;
                const float b0 = bias[n], b1 = bias[n + 1];
                float v00 = acc[mi][ni][0] + b0;
                float v01 = acc[mi][ni][1] + b1;
                float v10 = acc[mi][ni][2] + b0;
                float v11 = acc[mi][ni][3] + b1;
                if (MODE == 0) {
                    *(float2*)(Y + (size_t)m * DM_ + n)       = make_float2(v00, v01);
                    *(float2*)(Y + (size_t)(m + 8) * DM_ + n) = make_float2(v10, v11);
                } else {
                    if (z == 0) { v00 *= QSCALE; v01 *= QSCALE; v10 *= QSCALE; v11 *= QSCALE; }
                    const int h_ = n >> 6, d_ = n & (HD_ - 1);
                    if (z == 2) {
                        {
                            const int b_ = m >> 11, s_ = m & (S_ - 1);
                            __half* base = g_Vt + (((size_t)b_ * H_ + h_) * HD_ + d_) * S_ + s_;
                            base[0]  = __float2half_rn(v00);
                            base[S_] = __float2half_rn(v01);
                        }
                        {
                            const int m2 = m + 8;
                            const int b_ = m2 >> 11, s_ = m2 & (S_ - 1);
                            __half* base = g_Vt + (((size_t)b_ * H_ + h_) * HD_ + d_) * S_ + s_;
                            base[0]  = __float2half_rn(v10);
                            base[S_] = __float2half_rn(v11);
                        }
                    } else {
                        __half* dst = (z == 0) ? g_Q : g_K;
                        {
                            const int b_ = m >> 11, s_ = m & (S_ - 1);
                            *(uint32_t*)(dst + (((size_t)b_ * H_ + h_) * S_ + s_) * HD_ + d_) =
                                pk2(v00, v01);
                        }
                        {
                            const int m2 = m + 8;
                            const int b_ = m2 >> 11, s_ = m2 & (S_ - 1);
                            *(uint32_t*)(dst + (((size_t)b_ * H_ + h_) * S_ + s_) * HD_ + d_) =
                                pk2(v10, v11);
                        }
                    }
                }
            }
        }
    }
}

// ---------------------------------------------------------------------------
// Flash attention (persistent, round-12 structure: Bc=64, two 32-col chunks).
// CHANGE: S = Q K^T uses fp16-ACCUMULATE mma (rate experiment); PV stays fp32.
// exp2-domain softmax-one. O^T = V^T @ P^T.
// ---------------------------------------------------------------------------
#define KVB (64 * LDH * 2)   // 9216

__global__ __launch_bounds__(256, 2)
void attn_f16()
{
    extern __shared__ __half smh[];
    __half* Qs = smh;                           // 128*72 halves (reused as Ps)
    const uint32_t sQ = (uint32_t)__cvta_generic_to_shared(Qs);
    const uint32_t sK = sQ + 128 * LDH * 2;
    const uint32_t sV = sK + 2 * KVB;

    const int tid  = threadIdx.x;
    const int warp = tid >> 5, lane = tid & 31;
    const int g = lane >> 2, tg = lane & 3;

    const int q_base  = (warp * 16 + (lane & 15)) * LDH + ((lane >> 4) << 3);
    const int k_base  = (((lane >> 4) << 3) + (lane & 7)) * LDH
                      + (((lane >> 3) & 1) << 3);
    const int p_base  = q_base;
    const int vt_base = (lane & 15) * LDH + ((lane >> 4) << 3);
    const int qrow = warp * 16 + g;

    for (int item = blockIdx.x; item < 512; item += gridDim.x) {
        const int bh = item & 31;
        const int q0blk = (item >> 5) * 128;
        const int b = bh >> 4, h = bh & (H_ - 1);

        const __half* Qg  = g_Q + ((size_t)bh * S_ + q0blk) * HD_;
        const __half* Kg  = g_K + (size_t)bh * S_ * HD_;
        const __half* Vtg = g_Vt + (size_t)bh * HD_ * S_;

#pragma unroll
        for (int i = 0; i < 2; i++) {
            const int f = tid + 256 * i;
            const int row = f >> 3, ch = (f & 7) << 3;
            const uint32_t off = (uint32_t)(row * LDH + ch) << 1;
            cpa16(sK + off, Kg + (size_t)row * HD_ + ch);
            cpa16(sV + off, Vtg + (size_t)row * S_ + ch);
        }
        CP_COMMIT();

#pragma unroll
        for (int i = 0; i < 4; i++) {
            const int f = tid + 256 * i;
            const int row = f >> 3, ch = (f & 7) << 3;
            *(uint4*)((char*)Qs + ((size_t)(row * LDH + ch) << 1)) =
                *(const uint4*)(Qg + (size_t)row * HD_ + ch);
        }
        __syncthreads();

        uint32_t qf[4][4];
#pragma unroll
        for (int ks = 0; ks < 4; ks++)
            ldsm4(qf[ks], sQ + ((uint32_t)(q_base + ks * 16) << 1));
        __syncthreads();   // Qs now reusable as Ps

        float oacc[4][2][4];
#pragma unroll
        for (int i = 0; i < 4; i++)
#pragma unroll
            for (int j = 0; j < 2; j++)
#pragma unroll
                for (int k = 0; k < 4; k++) oacc[i][j][k] = 0.0f;

        float m0 = 0.0f, m1 = 0.0f;   // virtual zero logit (log2 domain)
        float l0 = 1.0f, l1 = 1.0f;

        for (int t = 0; t < 32; t++) {
            CP_WAIT0();
            __syncthreads();

            if (t + 1 < 32) {
                const size_t gofs = (size_t)(t + 1) * 64;
                const uint32_t bK = (uint32_t)(((t + 1) & 1) * KVB);
#pragma unroll
                for (int i = 0; i < 2; i++) {
                    const int f = tid + 256 * i;
                    const int row = f >> 3, ch = (f & 7) << 3;
                    const uint32_t off = (uint32_t)(row * LDH + ch) << 1;
                    cpa16(sK + bK + off, Kg + (gofs + row) * HD_ + ch);
                    cpa16(sV + bK + off, Vtg + (size_t)row * S_ + gofs + ch);
                }
                CP_COMMIT();
            }

            const uint32_t sKb = sK + (uint32_t)((t & 1) * KVB);
            const uint32_t sVb = sV + (uint32_t)((t & 1) * KVB);

#pragma unroll
            for (int c = 0; c < 2; c++) {
                const int colbase = c * 32;

                // S chunk = Q @ K^T with fp16 accumulate (rate experiment)
                uint32_t sh[4][2];
#pragma unroll
                for (int nt = 0; nt < 4; nt++) { sh[nt][0] = 0u; sh[nt][1] = 0u; }

#pragma unroll
                for (int ks = 0; ks < 4; ks++) {
#pragma unroll
                    for (int p = 0; p < 2; p++) {
                        uint32_t kf[4];
                        ldsm4(kf, sKb + ((uint32_t)(k_base + (colbase + p * 16) * LDH
                                                    + ks * 16) << 1));
                        mma_f16h(sh[2 * p],     qf[ks][0], qf[ks][1], qf[ks][2], qf[ks][3],
                                 kf[0], kf[1]);
                        mma_f16h(sh[2 * p + 1], qf[ks][0], qf[ks][1], qf[ks][2], qf[ks][3],
                                 kf[2], kf[3]);
                    }
                }

                // unpack to fp32 for softmax
                float s[4][4];
#pragma unroll
                for (int nt = 0; nt < 4; nt++) {
                    float2 lo = __half22float2(*(__half2*)&sh[nt][0]);
                    float2 hi = __half22float2(*(__half2*)&sh[nt][1]);
                    s[nt][0] = lo.x; s[nt][1] = lo.y;
                    s[nt][2] = hi.x; s[nt][3] = hi.y;
                }

                // online softmax-one update
                float rm0 = m0, rm1 = m1;
#pragma unroll
                for (int nt = 0; nt < 4; nt++) {
                    rm0 = fmaxf(rm0, fmaxf(s[nt][0], s[nt][1]));
                    rm1 = fmaxf(rm1, fmaxf(s[nt][2], s[nt][3]));
                }
                rm0 = fmaxf(rm0, __shfl_xor_sync(0xffffffffu, rm0, 1));
                rm0 = fmaxf(rm0, __shfl_xor_sync(0xffffffffu, rm0, 2));
                rm1 = fmaxf(rm1, __shfl_xor_sync(0xffffffffu, rm1, 1));
                rm1 = fmaxf(rm1, __shfl_xor_sync(0xffffffffu, rm1, 2));

                const float corr0 = ex2(m0 - rm0);
                const float corr1 = ex2(m1 - rm1);

                float ls0 = 0.0f, ls1 = 0.0f;
#pragma unroll
                for (int nt = 0; nt < 4; nt++) {
                    const float p00 = ex2(s[nt][0] - rm0);
                    const float p01 = ex2(s[nt][1] - rm0);
                    const float p10 = ex2(s[nt][2] - rm1);
                    const float p11 = ex2(s[nt][3] - rm1);
                    ls0 += p00 + p01;
                    ls1 += p10 + p11;
                    const int col = colbase + nt * 8 + 2 * tg;
                    *(uint32_t*)&Qs[qrow * LDH + col]       = pk2(p00, p01);
                    *(uint32_t*)&Qs[(qrow + 8) * LDH + col] = pk2(p10, p11);
                }
                ls0 += __shfl_xor_sync(0xffffffffu, ls0, 1);
                ls0 += __shfl_xor_sync(0xffffffffu, ls0, 2);
                ls1 += __shfl_xor_sync(0xffffffffu, ls1, 1);
                ls1 += __shfl_xor_sync(0xffffffffu, ls1, 2);
                l0 = l0 * corr0 + ls0; m0 = rm0;
                l1 = l1 * corr1 + ls1; m1 = rm1;
                __syncwarp();

#pragma unroll
                for (int nt = 0; nt < 2; nt++) {
                    const int ql0 = 2 * tg, ql1 = 2 * tg + 1;
                    float c0a = __shfl_sync(0xffffffffu, corr0, ql0 * 4);
                    float c0b = __shfl_sync(0xffffffffu, corr1, ql0 * 4);
                    float c1a = __shfl_sync(0xffffffffu, corr0, ql1 * 4);
                    float c1b = __shfl_sync(0xffffffffu, corr1, ql1 * 4);
                    const float cq0 = (nt == 0) ? c0a : c0b;
                    const float cq1 = (nt == 0) ? c1a : c1b;
#pragma unroll
                    for (int dt = 0; dt < 4; dt++) {
                        oacc[dt][nt][0] *= cq0;
                        oacc[dt][nt][1] *= cq1;
                        oacc[dt][nt][2] *= cq0;
                        oacc[dt][nt][3] *= cq1;
                    }
                }

                // O^T += V^T @ P^T (fp32 accumulate — precision-critical)
#pragma unroll
                for (int ks2 = 0; ks2 < 2; ks2++) {
                    const int kk = colbase + ks2 * 16;
                    uint32_t pr[4];
                    ldsm4(pr, sQ + ((uint32_t)(p_base + kk) << 1));
#pragma unroll
                    for (int dt = 0; dt < 4; dt++) {
                        uint32_t vf[4];
                        ldsm4(vf, sVb + ((uint32_t)(vt_base + dt * 16 * LDH + kk) << 1));
                        mma_f16(oacc[dt][0], vf[0], vf[1], vf[2], vf[3], pr[0], pr[2]);
                        mma_f16(oacc[dt][1], vf[0], vf[1], vf[2], vf[3], pr[1], pr[3]);
                    }
                }
            }
        }

        // finalize: divide by l, store O^T frags (fp16) to g_O
        const float inv0 = 1.0f / l0;
        const float inv1 = 1.0f / l1;
        float ivq[2][2];
#pragma unroll
        for (int nt = 0; nt < 2; nt++) {
            const int ql0 = 2 * tg, ql1 = 2 * tg + 1;
            float a0 = __shfl_sync(0xffffffffu, inv0, ql0 * 4);
            float b0 = __shfl_sync(0xffffffffu, inv1, ql0 * 4);
            float a1 = __shfl_sync(0xffffffffu, inv0, ql1 * 4);
            float b1 = __shfl_sync(0xffffffffu, inv1, ql1 * 4);
            ivq[nt][0] = (nt == 0) ? a0 : b0;
            ivq[nt][1] = (nt == 0) ? a1 : b1;
        }

        const size_t obase = ((size_t)(b * S_ + q0blk + warp * 16)) * DM_ + h * HD_;
#pragma unroll
        for (int dt = 0; dt < 4; dt++) {
#pragma unroll
            for (int nt = 0; nt < 2; nt++) {
                const int d  = dt * 16 + g;
                const int ql = nt * 8 + 2 * tg;
                g_O[obase + (size_t)ql * DM_ + d]           = __float2half_rn(oacc[dt][nt][0] * ivq[nt][0]);
                g_O[obase + (size_t)(ql + 1) * DM_ + d]     = __float2half_rn(oacc[dt][nt][1] * ivq[nt][1]);
                g_O[obase + (size_t)ql * DM_ + d + 8]       = __float2half_rn(oacc[dt][nt][2] * ivq[nt][0]);
                g_O[obase + (size_t)(ql + 1) * DM_ + d + 8] = __float2half_rn(oacc[dt][nt][3] * ivq[nt][1]);
            }
        }
        __syncthreads();   // smem safe to reuse for next item
    }
}

// ---------------------------------------------------------------------------
// Launch (only harness pointers cross the host/device boundary)
// ---------------------------------------------------------------------------
extern "C" void kernel_launch(void* const* d_in, const int* in_sizes, int n_in,
                              void* d_out, int out_size)
{
    const float* query = (const float*)d_in[0];
    const float* key   = (const float*)d_in[1];
    const float* value = (const float*)d_in[2];
    const float* bq = (const float*)d_in[4];
    const float* bk = (const float*)d_in[6];
    const float* bv = (const float*)d_in[8];
    const float* bo = (const float*)d_in[10];
    float* out = (float*)d_out;

    const int gemm_smem = 4 * GTILEB;                 // 73728
    const int attn_smem = 128 * LDH * 2 + 4 * KVB;    // 55296
    const int PGRID = 296;

    cudaFuncSetAttribute(gemm_f16<0>, cudaFuncAttributeMaxDynamicSharedMemorySize, gemm_smem);
    cudaFuncSetAttribute(gemm_f16<1>, cudaFuncAttributeMaxDynamicSharedMemorySize, gemm_smem);
    cudaFuncSetAttribute(attn_f16, cudaFuncAttributeMaxDynamicSharedMemorySize, attn_smem);

    prep_half<<<dim3(1024, 7), 256>>>(query, key, value,
                                      (const float*)d_in[3], (const float*)d_in[5],
                                      (const float*)d_in[7], (const float*)d_in[9]);

    gemm_f16<1><<<PGRID, 256, gemm_smem>>>(bq, bk, bv, nullptr);

    attn_f16<<<PGRID, 256, attn_smem>>>();

    gemm_f16<0><<<256, 256, gemm_smem>>>(bo, nullptr, nullptr, out);
}

// round 17
// speedup vs baseline: 1.1032x; 1.0301x over previous
#include <cuda_runtime.h>
#include <cuda_fp16.h>
#include <cstdint>
#include <math.h>

#define B_ 2
#define S_ 2048
#define DM_ 1024
#define H_ 16
#define HD_ 64
#define MTOT (B_ * S_)      // 4096
#define QSCALE 0.18033688f  // 0.125 * log2(e)

#define fu __float_as_uint
#define uf __uint_as_float

// Scratch (allocation-free __device__ globals; referenced ONLY in device code)
__device__ __half g_Q[(size_t)B_ * H_ * S_ * HD_];
__device__ __half g_K[(size_t)B_ * H_ * S_ * HD_];
__device__ __half g_Vt[(size_t)B_ * H_ * HD_ * S_];
__device__ __half g_O[(size_t)B_ * S_ * DM_];
__device__ __half g_Xq[(size_t)MTOT * DM_];
__device__ __half g_Xk[(size_t)MTOT * DM_];
__device__ __half g_Xv[(size_t)MTOT * DM_];
__device__ __half g_Wq[(size_t)DM_ * DM_];
__device__ __half g_Wk[(size_t)DM_ * DM_];
__device__ __half g_Wv[(size_t)DM_ * DM_];
__device__ __half g_Wo[(size_t)DM_ * DM_];

// Work queue + dependency counters (zero-init; last finisher resets -> replay-safe)
__device__ int g_work;
__device__ int g_done;
__device__ int g_attn_done;
__device__ int g_ready[24];   // [bn_block][z] -> counts to 32

#define N_QKV 768
#define N_ATT 512
#define N_OUT 256
#define N_TOT (N_QKV + N_ATT + N_OUT)

__device__ __forceinline__ uint32_t pk2(float a, float b) {
    __half2 h = __floats2half2_rn(a, b);
    return *reinterpret_cast<uint32_t*>(&h);
}

__device__ __forceinline__ float ex2(float x) {
    float r;
    asm("ex2.approx.ftz.f32 %0, %1;" : "=f"(r) : "f"(x));
    return r;
}

__device__ __forceinline__ void mma_f16(float c[4],
                                        uint32_t a0, uint32_t a1, uint32_t a2, uint32_t a3,
                                        uint32_t b0, uint32_t b1) {
    asm volatile(
        "mma.sync.aligned.m16n8k16.row.col.f32.f16.f16.f32 "
        "{%0,%1,%2,%3}, {%4,%5,%6,%7}, {%8,%9}, {%0,%1,%2,%3};\n"
        : "+f"(c[0]), "+f"(c[1]), "+f"(c[2]), "+f"(c[3])
        : "r"(a0), "r"(a1), "r"(a2), "r"(a3), "r"(b0), "r"(b1));
}

__device__ __forceinline__ void mma_f16h(uint32_t c[2],
                                         uint32_t a0, uint32_t a1, uint32_t a2, uint32_t a3,
                                         uint32_t b0, uint32_t b1) {
    asm volatile(
        "mma.sync.aligned.m16n8k16.row.col.f16.f16.f16.f16 "
        "{%0,%1}, {%2,%3,%4,%5}, {%6,%7}, {%0,%1};\n"
        : "+r"(c[0]), "+r"(c[1])
        : "r"(a0), "r"(a1), "r"(a2), "r"(a3), "r"(b0), "r"(b1));
}

__device__ __forceinline__ void ldsm4(uint32_t r[4], uint32_t addr) {
    asm volatile("ldmatrix.sync.aligned.m8n8.x4.shared.b16 {%0,%1,%2,%3}, [%4];"
                 : "=r"(r[0]), "=r"(r[1]), "=r"(r[2]), "=r"(r[3]) : "r"(addr));
}

__device__ __forceinline__ void cpa16(uint32_t dst, const void* src) {
    asm volatile("cp.async.cg.shared.global [%0], [%1], 16;" :: "r"(dst), "l"(src));
}
#define CP_COMMIT() asm volatile("cp.async.commit_group;")
#define CP_WAIT0()  asm volatile("cp.async.wait_group 0;")

#define LDH 72
#define GTILEB (128 * LDH * 2)   // 18432
#define KVB (64 * LDH * 2)       // 9216

// ---------------------------------------------------------------------------
// Prep: convert inputs and weights to fp16 (separate launch; BW-bound)
// ---------------------------------------------------------------------------
__global__ void prep_half(const float* __restrict__ q, const float* __restrict__ k,
                          const float* __restrict__ v, const float* __restrict__ wq,
                          const float* __restrict__ wk, const float* __restrict__ wv,
                          const float* __restrict__ wo)
{
    const float* src; __half* dst; int n;
    switch (blockIdx.y) {
        case 0: src = q;  dst = g_Xq; n = MTOT * DM_; break;
        case 1: src = k;  dst = g_Xk; n = MTOT * DM_; break;
        case 2: src = v;  dst = g_Xv; n = MTOT * DM_; break;
        case 3: src = wq; dst = g_Wq; n = DM_ * DM_;  break;
        case 4: src = wk; dst = g_Wk; n = DM_ * DM_;  break;
        case 5: src = wv; dst = g_Wv; n = DM_ * DM_;  break;
        default: src = wo; dst = g_Wo; n = DM_ * DM_; break;
    }
    const int n8 = n >> 3;
    for (int i = blockIdx.x * blockDim.x + threadIdx.x; i < n8;
         i += gridDim.x * blockDim.x) {
        float4 x0 = ((const float4*)src)[2 * i];
        float4 x1 = ((const float4*)src)[2 * i + 1];
        uint4 o;
        o.x = pk2(x0.x, x0.y); o.y = pk2(x0.z, x0.w);
        o.z = pk2(x1.x, x1.y); o.w = pk2(x1.z, x1.w);
        ((uint4*)dst)[i] = o;
    }
}

// ---------------------------------------------------------------------------
// One GEMM tile item (128x128): MODE 1 = QKV (z selects), MODE 0 = out proj.
// ---------------------------------------------------------------------------
template <int MODE>
__device__ __forceinline__ void gemm_one(__half* smh, int z, int bm, int bn,
                                         const float* __restrict__ bias,
                                         float* __restrict__ Y)
{
    const uint32_t sA = (uint32_t)__cvta_generic_to_shared(smh);
    const uint32_t sB = sA + GTILEB;

    const int tid  = threadIdx.x;
    const int warp = tid >> 5, lane = tid & 31;
    const int g  = lane >> 2, tg = lane & 3;
    const int wm = warp >> 2, wn = warp & 3;

    const int a_base = (wm * 64 + (lane & 15)) * LDH + ((lane >> 4) << 3);
    const int b_base = (wn * 32 + ((lane >> 4) << 3) + (lane & 7)) * LDH
                     + (((lane >> 3) & 1) << 3);

    const __half* X = (MODE == 0) ? g_O : (z == 0) ? g_Xq : (z == 1) ? g_Xk : g_Xv;
    const __half* W = (MODE == 0) ? g_Wo : (z == 0) ? g_Wq : (z == 1) ? g_Wk : g_Wv;

    float acc[4][4][4];
#pragma unroll
    for (int i = 0; i < 4; i++)
#pragma unroll
        for (int j = 0; j < 4; j++)
#pragma unroll
            for (int k = 0; k < 4; k++) acc[i][j][k] = 0.0f;

#pragma unroll
    for (int i = 0; i < 4; i++) {
        const int f = tid + 256 * i;
        const int row = f >> 3, ch = (f & 7) << 3;
        const uint32_t off = (uint32_t)(row * LDH + ch) << 1;
        cpa16(sA + off, X + (size_t)(bm + row) * DM_ + ch);
        cpa16(sB + off, W + (size_t)(bn + row) * DM_ + ch);
    }
    CP_COMMIT();

    for (int t = 0; t < 16; t++) {
        CP_WAIT0();
        __syncthreads();

        if (t + 1 < 16) {
            const int k0 = (t + 1) * 64;
            const uint32_t bufo = (uint32_t)(((t + 1) & 1) * 2 * GTILEB);
#pragma unroll
            for (int i = 0; i < 4; i++) {
                const int f = tid + 256 * i;
                const int row = f >> 3, ch = (f & 7) << 3;
                const uint32_t off = bufo + ((uint32_t)(row * LDH + ch) << 1);
                cpa16(sA + off, X + (size_t)(bm + row) * DM_ + k0 + ch);
                cpa16(sB + off, W + (size_t)(bn + row) * DM_ + k0 + ch);
            }
            CP_COMMIT();
        }

        const uint32_t bufb = (uint32_t)((t & 1) * 2 * GTILEB);
        const uint32_t sAb = sA + bufb;
        const uint32_t sBb = sB + bufb;

        uint32_t af[2][4][4], bf[2][2][4];
#pragma unroll
        for (int mi = 0; mi < 4; mi++)
            ldsm4(af[0][mi], sAb + ((uint32_t)(a_base + mi * 16 * LDH) << 1));
#pragma unroll
        for (int p = 0; p < 2; p++)
            ldsm4(bf[0][p], sBb + ((uint32_t)(b_base + p * 16 * LDH) << 1));

#pragma unroll
        for (int ks = 0; ks < 4; ks++) {
            const int cur = ks & 1, nxt = cur ^ 1;
            if (ks < 3) {
                const int kk = (ks + 1) * 16;
#pragma unroll
                for (int mi = 0; mi < 4; mi++)
                    ldsm4(af[nxt][mi],
                          sAb + ((uint32_t)(a_base + mi * 16 * LDH + kk) << 1));
#pragma unroll
                for (int p = 0; p < 2; p++)
                    ldsm4(bf[nxt][p],
                          sBb + ((uint32_t)(b_base + p * 16 * LDH + kk) << 1));
            }
#pragma unroll
            for (int mi = 0; mi < 4; mi++)
#pragma unroll
                for (int p = 0; p < 2; p++) {
                    mma_f16(acc[mi][2 * p],
                            af[cur][mi][0], af[cur][mi][1], af[cur][mi][2], af[cur][mi][3],
                            bf[cur][p][0], bf[cur][p][1]);
                    mma_f16(acc[mi][2 * p + 1],
                            af[cur][mi][0], af[cur][mi][1], af[cur][mi][2], af[cur][mi][3],
                            bf[cur][p][2], bf[cur][p][3]);
                }
        }
    }

#pragma unroll
    for (int mi = 0; mi < 4; mi++) {
#pragma unroll
        for (int ni = 0; ni < 4; ni++) {
            const int m = bm + wm * 64 + mi * 16 + g;
            const int n = bn + wn * 32 + ni * 8 + 2 * tg;
            const float b0 = bias[n], b1 = bias[n + 1];
            float v00 = acc[mi][ni][0] + b0;
            float v01 = acc[mi][ni][1] + b1;
            float v10 = acc[mi][ni][2] + b0;
            float v11 = acc[mi][ni][3] + b1;
            if (MODE == 0) {
                *(float2*)(Y + (size_t)m * DM_ + n)       = make_float2(v00, v01);
                *(float2*)(Y + (size_t)(m + 8) * DM_ + n) = make_float2(v10, v11);
            } else {
                if (z == 0) { v00 *= QSCALE; v01 *= QSCALE; v10 *= QSCALE; v11 *= QSCALE; }
                const int h_ = n >> 6, d_ = n & (HD_ - 1);
                if (z == 2) {
                    {
                        const int b_ = m >> 11, s_ = m & (S_ - 1);
                        __half* base = g_Vt + (((size_t)b_ * H_ + h_) * HD_ + d_) * S_ + s_;
                        base[0]  = __float2half_rn(v00);
                        base[S_] = __float2half_rn(v01);
                    }
                    {
                        const int m2 = m + 8;
                        const int b_ = m2 >> 11, s_ = m2 & (S_ - 1);
                        __half* base = g_Vt + (((size_t)b_ * H_ + h_) * HD_ + d_) * S_ + s_;
                        base[0]  = __float2half_rn(v10);
                        base[S_] = __float2half_rn(v11);
                    }
                } else {
                    __half* dst = (z == 0) ? g_Q : g_K;
                    {
                        const int b_ = m >> 11, s_ = m & (S_ - 1);
                        *(uint32_t*)(dst + (((size_t)b_ * H_ + h_) * S_ + s_) * HD_ + d_) =
                            pk2(v00, v01);
                    }
                    {
                        const int m2 = m + 8;
                        const int b_ = m2 >> 11, s_ = m2 & (S_ - 1);
                        *(uint32_t*)(dst + (((size_t)b_ * H_ + h_) * S_ + s_) * HD_ + d_) =
                            pk2(v10, v11);
                    }
                }
            }
        }
    }
}

// ---------------------------------------------------------------------------
// One attention item: (bh, q0blk) — 128 q-rows x full S. R15 internals
// (Bc=64, fp16-accum S, fp32-accum PV, exp2-domain softmax-one, O^T=V^T P^T).
// ---------------------------------------------------------------------------
__device__ __forceinline__ void attn_one(__half* smh, int bh, int q0blk)
{
    __half* Qs = smh;
    const uint32_t sQ = (uint32_t)__cvta_generic_to_shared(Qs);
    const uint32_t sK = sQ + 128 * LDH * 2;
    const uint32_t sV = sK + 2 * KVB;

    const int tid  = threadIdx.x;
    const int warp = tid >> 5, lane = tid & 31;
    const int g = lane >> 2, tg = lane & 3;
    const int b = bh >> 4, h = bh & (H_ - 1);

    const int q_base  = (warp * 16 + (lane & 15)) * LDH + ((lane >> 4) << 3);
    const int k_base  = (((lane >> 4) << 3) + (lane & 7)) * LDH
                      + (((lane >> 3) & 1) << 3);
    const int p_base  = q_base;
    const int vt_base = (lane & 15) * LDH + ((lane >> 4) << 3);
    const int qrow = warp * 16 + g;

    const __half* Qg  = g_Q + ((size_t)bh * S_ + q0blk) * HD_;
    const __half* Kg  = g_K + (size_t)bh * S_ * HD_;
    const __half* Vtg = g_Vt + (size_t)bh * HD_ * S_;

#pragma unroll
    for (int i = 0; i < 2; i++) {
        const int f = tid + 256 * i;
        const int row = f >> 3, ch = (f & 7) << 3;
        const uint32_t off = (uint32_t)(row * LDH + ch) << 1;
        cpa16(sK + off, Kg + (size_t)row * HD_ + ch);
        cpa16(sV + off, Vtg + (size_t)row * S_ + ch);
    }
    CP_COMMIT();

#pragma unroll
    for (int i = 0; i < 4; i++) {
        const int f = tid + 256 * i;
        const int row = f >> 3, ch = (f & 7) << 3;
        *(uint4*)((char*)Qs + ((size_t)(row * LDH + ch) << 1)) =
            *(const uint4*)(Qg + (size_t)row * HD_ + ch);
    }
    __syncthreads();

    uint32_t qf[4][4];
#pragma unroll
    for (int ks = 0; ks < 4; ks++)
        ldsm4(qf[ks], sQ + ((uint32_t)(q_base + ks * 16) << 1));
    __syncthreads();   // Qs now reusable as Ps

    float oacc[4][2][4];
#pragma unroll
    for (int i = 0; i < 4; i++)
#pragma unroll
        for (int j = 0; j < 2; j++)
#pragma unroll
            for (int k = 0; k < 4; k++) oacc[i][j][k] = 0.0f;

    float m0 = 0.0f, m1 = 0.0f;
    float l0 = 1.0f, l1 = 1.0f;

    for (int t = 0; t < 32; t++) {
        CP_WAIT0();
        __syncthreads();

        if (t + 1 < 32) {
            const size_t gofs = (size_t)(t + 1) * 64;
            const uint32_t bK = (uint32_t)(((t + 1) & 1) * KVB);
#pragma unroll
            for (int i = 0; i < 2; i++) {
                const int f = tid + 256 * i;
                const int row = f >> 3, ch = (f & 7) << 3;
                const uint32_t off = (uint32_t)(row * LDH + ch) << 1;
                cpa16(sK + bK + off, Kg + (gofs + row) * HD_ + ch);
                cpa16(sV + bK + off, Vtg + (size_t)row * S_ + gofs + ch);
            }
            CP_COMMIT();
        }

        const uint32_t sKb = sK + (uint32_t)((t & 1) * KVB);
        const uint32_t sVb = sV + (uint32_t)((t & 1) * KVB);

#pragma unroll
        for (int c = 0; c < 2; c++) {
            const int colbase = c * 32;

            uint32_t sh[4][2];
#pragma unroll
            for (int nt = 0; nt < 4; nt++) { sh[nt][0] = 0u; sh[nt][1] = 0u; }

#pragma unroll
            for (int ks = 0; ks < 4; ks++) {
#pragma unroll
                for (int p = 0; p < 2; p++) {
                    uint32_t kf[4];
                    ldsm4(kf, sKb + ((uint32_t)(k_base + (colbase + p * 16) * LDH
                                                + ks * 16) << 1));
                    mma_f16h(sh[2 * p],     qf[ks][0], qf[ks][1], qf[ks][2], qf[ks][3],
                             kf[0], kf[1]);
                    mma_f16h(sh[2 * p + 1], qf[ks][0], qf[ks][1], qf[ks][2], qf[ks][3],
                             kf[2], kf[3]);
                }
            }

            float s[4][4];
#pragma unroll
            for (int nt = 0; nt < 4; nt++) {
                float2 lo = __half22float2(*(__half2*)&sh[nt][0]);
                float2 hi = __half22float2(*(__half2*)&sh[nt][1]);
                s[nt][0] = lo.x; s[nt][1] = lo.y;
                s[nt][2] = hi.x; s[nt][3] = hi.y;
            }

            float rm0 = m0, rm1 = m1;
#pragma unroll
            for (int nt = 0; nt < 4; nt++) {
                rm0 = fmaxf(rm0, fmaxf(s[nt][0], s[nt][1]));
                rm1 = fmaxf(rm1, fmaxf(s[nt][2], s[nt][3]));
            }
            rm0 = fmaxf(rm0, __shfl_xor_sync(0xffffffffu, rm0, 1));
            rm0 = fmaxf(rm0, __shfl_xor_sync(0xffffffffu, rm0, 2));
            rm1 = fmaxf(rm1, __shfl_xor_sync(0xffffffffu, rm1, 1));
            rm1 = fmaxf(rm1, __shfl_xor_sync(0xffffffffu, rm1, 2));

            const float corr0 = ex2(m0 - rm0);
            const float corr1 = ex2(m1 - rm1);

            float ls0 = 0.0f, ls1 = 0.0f;
#pragma unroll
            for (int nt = 0; nt < 4; nt++) {
                const float p00 = ex2(s[nt][0] - rm0);
                const float p01 = ex2(s[nt][1] - rm0);
                const float p10 = ex2(s[nt][2] - rm1);
                const float p11 = ex2(s[nt][3] - rm1);
                ls0 += p00 + p01;
                ls1 += p10 + p11;
                const int col = colbase + nt * 8 + 2 * tg;
                *(uint32_t*)&Qs[qrow * LDH + col]       = pk2(p00, p01);
                *(uint32_t*)&Qs[(qrow + 8) * LDH + col] = pk2(p10, p11);
            }
            ls0 += __shfl_xor_sync(0xffffffffu, ls0, 1);
            ls0 += __shfl_xor_sync(0xffffffffu, ls0, 2);
            ls1 += __shfl_xor_sync(0xffffffffu, ls1, 1);
            ls1 += __shfl_xor_sync(0xffffffffu, ls1, 2);
            l0 = l0 * corr0 + ls0; m0 = rm0;
            l1 = l1 * corr1 + ls1; m1 = rm1;
            __syncwarp();

#pragma unroll
            for (int nt = 0; nt < 2; nt++) {
                const int ql0 = 2 * tg, ql1 = 2 * tg + 1;
                float c0a = __shfl_sync(0xffffffffu, corr0, ql0 * 4);
                float c0b = __shfl_sync(0xffffffffu, corr1, ql0 * 4);
                float c1a = __shfl_sync(0xffffffffu, corr0, ql1 * 4);
                float c1b = __shfl_sync(0xffffffffu, corr1, ql1 * 4);
                const float cq0 = (nt == 0) ? c0a : c0b;
                const float cq1 = (nt == 0) ? c1a : c1b;
#pragma unroll
                for (int dt = 0; dt < 4; dt++) {
                    oacc[dt][nt][0] *= cq0;
                    oacc[dt][nt][1] *= cq1;
                    oacc[dt][nt][2] *= cq0;
                    oacc[dt][nt][3] *= cq1;
                }
            }

#pragma unroll
            for (int ks2 = 0; ks2 < 2; ks2++) {
                const int kk = colbase + ks2 * 16;
                uint32_t pr[4];
                ldsm4(pr, sQ + ((uint32_t)(p_base + kk) << 1));
#pragma unroll
                for (int dt = 0; dt < 4; dt++) {
                    uint32_t vf[4];
                    ldsm4(vf, sVb + ((uint32_t)(vt_base + dt * 16 * LDH + kk) << 1));
                    mma_f16(oacc[dt][0], vf[0], vf[1], vf[2], vf[3], pr[0], pr[2]);
                    mma_f16(oacc[dt][1], vf[0], vf[1], vf[2], vf[3], pr[1], pr[3]);
                }
            }
        }
    }

    const float inv0 = 1.0f / l0;
    const float inv1 = 1.0f / l1;
    float ivq[2][2];
#pragma unroll
    for (int nt = 0; nt < 2; nt++) {
        const int ql0 = 2 * tg, ql1 = 2 * tg + 1;
        float a0 = __shfl_sync(0xffffffffu, inv0, ql0 * 4);
        float b0 = __shfl_sync(0xffffffffu, inv1, ql0 * 4);
        float a1 = __shfl_sync(0xffffffffu, inv0, ql1 * 4);
        float b1 = __shfl_sync(0xffffffffu, inv1, ql1 * 4);
        ivq[nt][0] = (nt == 0) ? a0 : b0;
        ivq[nt][1] = (nt == 0) ? a1 : b1;
    }

    const size_t obase = ((size_t)(b * S_ + q0blk + warp * 16)) * DM_ + h * HD_;
#pragma unroll
    for (int dt = 0; dt < 4; dt++) {
#pragma unroll
        for (int nt = 0; nt < 2; nt++) {
            const int d  = dt * 16 + g;
            const int ql = nt * 8 + 2 * tg;
            g_O[obase + (size_t)ql * DM_ + d]           = __float2half_rn(oacc[dt][nt][0] * ivq[nt][0]);
            g_O[obase + (size_t)(ql + 1) * DM_ + d]     = __float2half_rn(oacc[dt][nt][1] * ivq[nt][1]);
            g_O[obase + (size_t)ql * DM_ + d + 8]       = __float2half_rn(oacc[dt][nt][2] * ivq[nt][0]);
            g_O[obase + (size_t)(ql + 1) * DM_ + d + 8] = __float2half_rn(oacc[dt][nt][3] * ivq[nt][1]);
        }
    }
}

// ---------------------------------------------------------------------------
// Fused work-stealing kernel: 1536 items with fine-grained dependencies.
// QKV items bn-block-major; attention items wait on their 3 ready counters;
// out items wait on attn_done. nanosleep backoff in spins.
// ---------------------------------------------------------------------------
__global__ __launch_bounds__(256, 2)
void fused_work(const float* __restrict__ bq, const float* __restrict__ bk,
                const float* __restrict__ bv, const float* __restrict__ bo,
                float* __restrict__ out)
{
    extern __shared__ __half smh[];
    __shared__ int s_item;
    const int tid = threadIdx.x;

    for (;;) {
        __syncthreads();   // all threads done with previous item's smem
        if (tid == 0) s_item = atomicAdd(&g_work, 1);
        __syncthreads();
        const int it = s_item;
        if (it >= N_TOT) break;

        if (it < N_QKV) {
            // QKV item: bn-block major
            const int bnb = it / 96;
            const int r   = it - bnb * 96;
            const int z   = r >> 5;
            const int bm  = (r & 31) * 128;
            const float* bias = (z == 0) ? bq : (z == 1) ? bk : bv;
            gemm_one<1>(smh, z, bm, bnb * 128, bias, nullptr);
            __syncthreads();
            if (tid == 0) {
                __threadfence();
                atomicAdd(&g_ready[bnb * 3 + z], 1);
            }
        } else if (it < N_QKV + N_ATT) {
            const int a   = it - N_QKV;
            const int bnb = a >> 6;            // 8 bn-blocks x 64 items
            const int r   = a & 63;
            const int bhl = r >> 4;            // 0..3: (b, head-in-block)
            const int bh  = (bhl >> 1) * 16 + bnb * 2 + (bhl & 1);
            const int q0  = (r & 15) * 128;
            // wait for this bn-block's Q, K, V producer items
            if (tid == 0) {
                volatile int* rc = g_ready + bnb * 3;
                while (rc[0] < 32 || rc[1] < 32 || rc[2] < 32) __nanosleep(128);
                __threadfence();
            }
            __syncthreads();
            attn_one(smh, bh, q0);
            __syncthreads();
            if (tid == 0) {
                __threadfence();
                atomicAdd(&g_attn_done, 1);
            }
        } else {
            const int o  = it - N_QKV - N_ATT;
            const int bn = (o & 7) * 128;
            const int bm = (o >> 3) * 128;
            if (tid == 0) {
                volatile int* ad = &g_attn_done;
                while (*ad < N_ATT) __nanosleep(128);
                __threadfence();
            }
            __syncthreads();
            gemm_one<0>(smh, 0, bm, bn, bo, out);
        }
    }

    // replay-safe reset by the last CTA to finish
    if (tid == 0) {
        const int d = atomicAdd(&g_done, 1);
        if (d == (int)gridDim.x - 1) {
            g_work = 0;
            g_attn_done = 0;
#pragma unroll
            for (int i = 0; i < 24; i++) g_ready[i] = 0;
            g_done = 0;
            __threadfence();
        }
    }
}

// ---------------------------------------------------------------------------
// Launch
// ---------------------------------------------------------------------------
extern "C" void kernel_launch(void* const* d_in, const int* in_sizes, int n_in,
                              void* d_out, int out_size)
{
    const int fused_smem = 4 * GTILEB;   // 73728 (gemm layout superset of attn's 55296)

    cudaFuncSetAttribute(fused_work, cudaFuncAttributeMaxDynamicSharedMemorySize, fused_smem);

    prep_half<<<dim3(1024, 7), 256>>>(
        (const float*)d_in[0], (const float*)d_in[1], (const float*)d_in[2],
        (const float*)d_in[3], (const float*)d_in[5],
        (const float*)d_in[7], (const float*)d_in[9]);

    fused_work<<<296, 256, fused_smem>>>(
        (const float*)d_in[4], (const float*)d_in[6],
        (const float*)d_in[8], (const float*)d_in[10],
        (float*)d_out);
}